// round 1
// baseline (speedup 1.0000x reference)
#include <cuda_runtime.h>
#include <math.h>

// Problem constants
#define B_DIM 2
#define CIN_DIM 512
#define L_DIM 1024
#define H_DIM 32
#define D_DIM 64
#define A_DIM 2048   // H*D

// Scratch (static device arrays; allocation-free per harness rules)
__device__ float g_q[B_DIM * A_DIM * L_DIM];                 // 16 MB
__device__ float g_k[B_DIM * A_DIM * L_DIM];                 // 16 MB
__device__ float g_v[B_DIM * A_DIM * L_DIM];                 // 16 MB
__device__ float g_p[B_DIM * H_DIM * L_DIM * L_DIM];         // 256 MB
__device__ float g_h[B_DIM * A_DIM * L_DIM];                 // 16 MB
__device__ float g_z[B_DIM * A_DIM * L_DIM];                 // 16 MB

enum { EPI_NONE = 0, EPI_BIAS = 1, EPI_BIAS_RELU = 2, EPI_RELU = 3, EPI_SCORES = 4 };

// Generic batched SGEMM: C[z] = op(A[z]) @ B[z] (+bias) (+relu / scores epilogue)
//  TRANSA=false: A row-major [M,K]   (element A[i*K+k])
//  TRANSA=true : A row-major [K,M]   (element A[k*M+i])  -> C = A^T B
//  B always row-major [K,N]. C row-major [M,N].
// Requirements: N % 128 == 0, K % 8 == 0. M guarded (may be < 128 or not multiple).
// TRANSA path requires M % 128 == 0 (true for its only use: scores, M=L=1024).
template <bool TRANSA, int EPI>
__global__ __launch_bounds__(256) void gemm128(
    const float* __restrict__ Ag, const float* __restrict__ Bg,
    const float* __restrict__ bias, float* __restrict__ Cg,
    int M, int N, int K,
    long long Abs, long long Bbs, long long Cbs)
{
    const float* Ap = Ag + (long long)blockIdx.z * Abs;
    const float* Bp = Bg + (long long)blockIdx.z * Bbs;
    float* Cp = Cg + (long long)blockIdx.z * Cbs;

    __shared__ float As[8][128];
    __shared__ float Bs[8][128];

    const int tx = threadIdx.x;          // 0..15
    const int ty = threadIdx.y;          // 0..15
    const int tid = ty * 16 + tx;        // 0..255
    const int row0 = blockIdx.y * 128;
    const int col0 = blockIdx.x * 128;

    float acc[8][8];
#pragma unroll
    for (int i = 0; i < 8; i++)
#pragma unroll
        for (int j = 0; j < 8; j++) acc[i][j] = 0.f;

    for (int k0 = 0; k0 < K; k0 += 8) {
        // --- load A tile into As[kk][mm] ---
        if (!TRANSA) {
            int r = tid >> 1;             // 0..127
            int c4 = (tid & 1) * 4;       // 0 or 4
            float4 v = make_float4(0.f, 0.f, 0.f, 0.f);
            if (row0 + r < M)
                v = *(const float4*)&Ap[(long long)(row0 + r) * K + (k0 + c4)];
            As[c4 + 0][r] = v.x;
            As[c4 + 1][r] = v.y;
            As[c4 + 2][r] = v.z;
            As[c4 + 3][r] = v.w;
        } else {
            int kk = tid >> 5;            // 0..7
            int mm = (tid & 31) * 4;      // 0..124
            float4 v = *(const float4*)&Ap[(long long)(k0 + kk) * M + (row0 + mm)];
            *(float4*)&As[kk][mm] = v;
        }
        // --- load B tile into Bs[kk][nn] ---
        {
            int kk = tid >> 5;
            int nn = (tid & 31) * 4;
            float4 v = *(const float4*)&Bp[(long long)(k0 + kk) * N + (col0 + nn)];
            *(float4*)&Bs[kk][nn] = v;
        }
        __syncthreads();

#pragma unroll
        for (int kk = 0; kk < 8; kk++) {
            float a[8], b[8];
#pragma unroll
            for (int i = 0; i < 8; i++) a[i] = As[kk][ty * 8 + i];
#pragma unroll
            for (int j = 0; j < 8; j++) b[j] = Bs[kk][tx * 8 + j];
#pragma unroll
            for (int i = 0; i < 8; i++)
#pragma unroll
                for (int j = 0; j < 8; j++) acc[i][j] += a[i] * b[j];
        }
        __syncthreads();
    }

    // --- epilogue ---
#pragma unroll
    for (int i = 0; i < 8; i++) {
        int r = row0 + ty * 8 + i;
        if (r < M) {
            float bv = 0.f;
            if (EPI == EPI_BIAS || EPI == EPI_BIAS_RELU) bv = bias[r];
#pragma unroll
            for (int j = 0; j < 8; j++) {
                int c = col0 + tx * 8 + j;
                float v = acc[i][j] + bv;
                if (EPI == EPI_SCORES)
                    v = (v - fabsf((float)(r - c))) * 0.125f;  // (+s_rel)/sqrt(D)
                if (EPI == EPI_RELU || EPI == EPI_BIAS_RELU)
                    v = fmaxf(v, 0.f);
                Cp[(long long)r * N + c] = v;
            }
        }
    }
}

// Row softmax over last axis + post-softmax triu mask (keep l <= m).
// One block (256 threads) per row; grid = (L, B*H).
__global__ __launch_bounds__(256) void softmax_mask(float* __restrict__ P)
{
    const int L = L_DIM;
    const int l = blockIdx.x;
    float* row = P + ((long long)blockIdx.y * L + l) * L;
    const int t = threadIdx.x;

    float v[4];
    float m = -1e30f;
#pragma unroll
    for (int i = 0; i < 4; i++) {
        v[i] = row[t + 256 * i];
        m = fmaxf(m, v[i]);
    }

    __shared__ float red[8];
    // block max
#pragma unroll
    for (int o = 16; o > 0; o >>= 1) m = fmaxf(m, __shfl_xor_sync(0xffffffffu, m, o));
    if ((t & 31) == 0) red[t >> 5] = m;
    __syncthreads();
    if (t < 32) {
        float x = (t < 8) ? red[t] : -1e30f;
#pragma unroll
        for (int o = 4; o > 0; o >>= 1) x = fmaxf(x, __shfl_xor_sync(0xffffffffu, x, o));
        if (t == 0) red[0] = x;
    }
    __syncthreads();
    m = red[0];

    float s = 0.f;
#pragma unroll
    for (int i = 0; i < 4; i++) {
        v[i] = expf(v[i] - m);
        s += v[i];
    }
    __syncthreads();  // red reuse
    // block sum
#pragma unroll
    for (int o = 16; o > 0; o >>= 1) s += __shfl_xor_sync(0xffffffffu, s, o);
    if ((t & 31) == 0) red[t >> 5] = s;
    __syncthreads();
    if (t < 32) {
        float x = (t < 8) ? red[t] : 0.f;
#pragma unroll
        for (int o = 4; o > 0; o >>= 1) x += __shfl_xor_sync(0xffffffffu, x, o);
        if (t == 0) red[0] = x;
    }
    __syncthreads();
    const float inv = 1.0f / red[0];

#pragma unroll
    for (int i = 0; i < 4; i++) {
        int c = t + 256 * i;
        row[c] = (l <= c) ? v[i] * inv : 0.f;
    }
}

extern "C" void kernel_launch(void* const* d_in, const int* in_sizes, int n_in,
                              void* d_out, int out_size)
{
    (void)in_sizes; (void)n_in; (void)out_size;
    const float* x  = (const float*)d_in[0];
    const float* Wq = (const float*)d_in[1];
    const float* bq = (const float*)d_in[2];
    const float* Wk = (const float*)d_in[3];
    const float* bk = (const float*)d_in[4];
    const float* Wv = (const float*)d_in[5];
    const float* bv = (const float*)d_in[6];
    const float* W1 = (const float*)d_in[7];
    const float* b1 = (const float*)d_in[8];
    const float* W2 = (const float*)d_in[9];
    const float* b2 = (const float*)d_in[10];
    float* out = (float*)d_out;

    float *q, *k, *v, *p, *h, *z;
    cudaGetSymbolAddress((void**)&q, g_q);
    cudaGetSymbolAddress((void**)&k, g_k);
    cudaGetSymbolAddress((void**)&v, g_v);
    cudaGetSymbolAddress((void**)&p, g_p);
    cudaGetSymbolAddress((void**)&h, g_h);
    cudaGetSymbolAddress((void**)&z, g_z);

    const long long AL = (long long)A_DIM * L_DIM;   // per-batch q/k/v/h/z stride
    const long long DL = (long long)D_DIM * L_DIM;   // per-head stride
    const long long PL = (long long)L_DIM * L_DIM;   // per-head P stride

    dim3 blk(16, 16);

    // 1) QKV projections: C[b] = W @ x[b] + bias ; M=2048, N=1024, K=512
    dim3 gproj(L_DIM / 128, A_DIM / 128, B_DIM);
    gemm128<false, EPI_BIAS><<<gproj, blk>>>(Wq, x, bq, q, A_DIM, L_DIM, CIN_DIM,
                                             0, (long long)CIN_DIM * L_DIM, AL);
    gemm128<false, EPI_BIAS><<<gproj, blk>>>(Wk, x, bk, k, A_DIM, L_DIM, CIN_DIM,
                                             0, (long long)CIN_DIM * L_DIM, AL);
    gemm128<false, EPI_BIAS><<<gproj, blk>>>(Wv, x, bv, v, A_DIM, L_DIM, CIN_DIM,
                                             0, (long long)CIN_DIM * L_DIM, AL);

    // 2) Scores per (b,h): S = q_h^T @ k_h, epilogue adds -|l-m| and scales 1/8
    //    M=N=L=1024, K=D=64; z = b*H+h
    dim3 gsc(L_DIM / 128, L_DIM / 128, B_DIM * H_DIM);
    gemm128<true, EPI_SCORES><<<gsc, blk>>>(q, k, nullptr, p, L_DIM, L_DIM, D_DIM,
                                            DL, DL, PL);

    // 3) Row softmax + post-softmax triu mask (in place on P)
    softmax_mask<<<dim3(L_DIM, B_DIM * H_DIM), 256>>>(p);

    // 4) Attn-out per (b,h): o = v_h @ P, ReLU ; M=64, N=1024, K=1024
    dim3 gao(L_DIM / 128, 1, B_DIM * H_DIM);
    gemm128<false, EPI_RELU><<<gao, blk>>>(v, p, nullptr, h, D_DIM, L_DIM, L_DIM,
                                           DL, PL, DL);

    // 5) Final MLP: z = relu(W1 @ h + b1) ; out = W2 @ z + b2 ; M=2048, N=1024, K=2048
    dim3 gf(L_DIM / 128, A_DIM / 128, B_DIM);
    gemm128<false, EPI_BIAS_RELU><<<gf, blk>>>(W1, h, b1, z, A_DIM, L_DIM, A_DIM,
                                               0, AL, AL);
    gemm128<false, EPI_BIAS><<<gf, blk>>>(W2, z, b2, out, A_DIM, L_DIM, A_DIM,
                                          0, AL, AL);
}

// round 2
// speedup vs baseline: 2.3164x; 2.3164x over previous
#include <cuda_runtime.h>
#include <cstdint>
#include <math.h>

// Problem constants
#define B_DIM 2
#define CIN_DIM 512
#define L_DIM 1024
#define H_DIM 32
#define D_DIM 64
#define A_DIM 2048   // H*D

// Scratch (static device arrays; allocation-free per harness rules)
__device__ float g_q[B_DIM * A_DIM * L_DIM];                 // 16 MB
__device__ float g_k[B_DIM * A_DIM * L_DIM];                 // 16 MB
__device__ float g_v[B_DIM * A_DIM * L_DIM];                 // 16 MB
__device__ float g_p[B_DIM * H_DIM * L_DIM * L_DIM];         // 256 MB
__device__ float g_h[B_DIM * A_DIM * L_DIM];                 // 16 MB
__device__ float g_z[B_DIM * A_DIM * L_DIM];                 // 16 MB

enum { EPI_NONE = 0, EPI_BIAS = 1, EPI_BIAS_RELU = 2, EPI_RELU = 3, EPI_SCORES = 4 };

__device__ __forceinline__ float cvt_tf32(float x) {
    uint32_t u;
    asm("cvt.rna.tf32.f32 %0, %1;" : "=r"(u) : "f"(x));
    return __uint_as_float(u);
}

__device__ __forceinline__ void mma_tf32(float c[4], const uint32_t a[4], const uint32_t b[2]) {
    asm volatile(
        "mma.sync.aligned.m16n8k8.row.col.f32.tf32.tf32.f32 "
        "{%0,%1,%2,%3}, {%4,%5,%6,%7}, {%8,%9}, {%0,%1,%2,%3};\n"
        : "+f"(c[0]), "+f"(c[1]), "+f"(c[2]), "+f"(c[3])
        : "r"(a[0]), "r"(a[1]), "r"(a[2]), "r"(a[3]), "r"(b[0]), "r"(b[1]));
}

// Batched TF32 tensor-core GEMM: C[z] = op(A[z]) @ B[z] (+epilogue)
//  TRANSA=false: A row-major [M,K];  TRANSA=true: A row-major [K,M] -> C = A^T B
//  B row-major [K,N], C row-major [M,N].
//  Requires: M % BM == 0, N % 128 == 0, K % 16 == 0.
template <int BM, bool TRANSA, int EPI>
__global__ __launch_bounds__(256) void gemm_tc(
    const float* __restrict__ Ag, const float* __restrict__ Bg,
    const float* __restrict__ bias, float* __restrict__ Cg,
    int M, int N, int K,
    long long Abs, long long Bbs, long long Cbs)
{
    constexpr int BN = 128, KC = 16;
    constexpr int ASTR = BM + 8;      // (BM+8) % 32 == 8 -> conflict-free frag loads
    constexpr int BSTR = BN + 8;
    constexpr int WMW = (BM == 128) ? 4 : 2;  // warps along M
    constexpr int WNW = 8 / WMW;              // warps along N
    constexpr int WTM = BM / WMW;             // 32
    constexpr int WTN = BN / WNW;             // 64 or 32
    constexpr int FM = WTM / 16;              // 2
    constexpr int FN = WTN / 8;               // 8 or 4
    constexpr int NA = (BM * KC / 4) / 256;   // float4 per thread for A (2 or 1)
    constexpr int NB = (BN * KC / 4) / 256;   // 2

    __shared__ float As[2][KC * ASTR];
    __shared__ float Bs[2][KC * BSTR];

    const float* Ap = Ag + (long long)blockIdx.z * Abs;
    const float* Bp = Bg + (long long)blockIdx.z * Bbs;
    float* Cp = Cg + (long long)blockIdx.z * Cbs;

    const int tid = threadIdx.x;
    const int lane = tid & 31;
    const int w = tid >> 5;
    const int wm = w % WMW, wn = w / WMW;
    const int row0 = blockIdx.y * BM;
    const int col0 = blockIdx.x * BN;

    float acc[FM][FN][4] = {};
    float4 pa[NA], pb[NB];

    auto fetch = [&](int k0) {
        if (!TRANSA) {
#pragma unroll
            for (int u = 0; u < NA; ++u) {
                int idx = tid + u * 256;
                int r = idx % BM, j = idx / BM;   // j in 0..3
                pa[u] = *(const float4*)&Ap[(long long)(row0 + r) * K + k0 + 4 * j];
            }
        } else {
#pragma unroll
            for (int u = 0; u < NA; ++u) {
                int idx = tid + u * 256;
                int mq = idx % (BM / 4), kk = idx / (BM / 4);
                pa[u] = *(const float4*)&Ap[(long long)(k0 + kk) * M + row0 + 4 * mq];
            }
        }
#pragma unroll
        for (int u = 0; u < NB; ++u) {
            int idx = tid + u * 256;
            int nq = idx % (BN / 4), kk = idx / (BN / 4);
            pb[u] = *(const float4*)&Bp[(long long)(k0 + kk) * N + col0 + 4 * nq];
        }
    };

    auto stage = [&](int buf) {
        if (!TRANSA) {
#pragma unroll
            for (int u = 0; u < NA; ++u) {
                int idx = tid + u * 256;
                int r = idx % BM, j = idx / BM;
                As[buf][(4 * j + 0) * ASTR + r] = cvt_tf32(pa[u].x);
                As[buf][(4 * j + 1) * ASTR + r] = cvt_tf32(pa[u].y);
                As[buf][(4 * j + 2) * ASTR + r] = cvt_tf32(pa[u].z);
                As[buf][(4 * j + 3) * ASTR + r] = cvt_tf32(pa[u].w);
            }
        } else {
#pragma unroll
            for (int u = 0; u < NA; ++u) {
                int idx = tid + u * 256;
                int mq = idx % (BM / 4), kk = idx / (BM / 4);
                float4 t;
                t.x = cvt_tf32(pa[u].x); t.y = cvt_tf32(pa[u].y);
                t.z = cvt_tf32(pa[u].z); t.w = cvt_tf32(pa[u].w);
                *(float4*)&As[buf][kk * ASTR + 4 * mq] = t;
            }
        }
#pragma unroll
        for (int u = 0; u < NB; ++u) {
            int idx = tid + u * 256;
            int nq = idx % (BN / 4), kk = idx / (BN / 4);
            float4 t;
            t.x = cvt_tf32(pb[u].x); t.y = cvt_tf32(pb[u].y);
            t.z = cvt_tf32(pb[u].z); t.w = cvt_tf32(pb[u].w);
            *(float4*)&Bs[buf][kk * BSTR + 4 * nq] = t;
        }
    };

    auto compute = [&](int buf) {
        const int row = lane >> 2, kcol = lane & 3;
#pragma unroll
        for (int ks = 0; ks < KC; ks += 8) {
            uint32_t af[FM][4];
#pragma unroll
            for (int f = 0; f < FM; ++f) {
                const float* Ab = &As[buf][ks * ASTR + wm * WTM + f * 16 + row];
                af[f][0] = __float_as_uint(Ab[kcol * ASTR]);
                af[f][1] = __float_as_uint(Ab[kcol * ASTR + 8]);
                af[f][2] = __float_as_uint(Ab[(kcol + 4) * ASTR]);
                af[f][3] = __float_as_uint(Ab[(kcol + 4) * ASTR + 8]);
            }
            uint32_t bf[FN][2];
#pragma unroll
            for (int g = 0; g < FN; ++g) {
                const float* Bb = &Bs[buf][ks * BSTR + wn * WTN + g * 8 + row];
                bf[g][0] = __float_as_uint(Bb[kcol * BSTR]);
                bf[g][1] = __float_as_uint(Bb[(kcol + 4) * BSTR]);
            }
#pragma unroll
            for (int f = 0; f < FM; ++f)
#pragma unroll
                for (int g = 0; g < FN; ++g)
                    mma_tf32(acc[f][g], af[f], bf[g]);
        }
    };

    const int nit = K / KC;
    fetch(0);
    stage(0);
    __syncthreads();
    for (int it = 0; it < nit; ++it) {
        int cur = it & 1;
        if (it + 1 < nit) fetch((it + 1) * KC);
        compute(cur);
        if (it + 1 < nit) {
            stage(cur ^ 1);
            __syncthreads();
        }
    }

    // Epilogue
#pragma unroll
    for (int f = 0; f < FM; ++f) {
        int r = row0 + wm * WTM + f * 16 + (lane >> 2);
        float b0v = 0.f, b8v = 0.f;
        if (EPI == EPI_BIAS || EPI == EPI_BIAS_RELU) { b0v = bias[r]; b8v = bias[r + 8]; }
#pragma unroll
        for (int g = 0; g < FN; ++g) {
            int c = col0 + wn * WTN + g * 8 + (lane & 3) * 2;
            float v0 = acc[f][g][0] + b0v;
            float v1 = acc[f][g][1] + b0v;
            float v2 = acc[f][g][2] + b8v;
            float v3 = acc[f][g][3] + b8v;
            if (EPI == EPI_SCORES) {
                v0 = (v0 - fabsf((float)(r - c))) * 0.125f;
                v1 = (v1 - fabsf((float)(r - c - 1))) * 0.125f;
                v2 = (v2 - fabsf((float)(r + 8 - c))) * 0.125f;
                v3 = (v3 - fabsf((float)(r + 8 - c - 1))) * 0.125f;
            }
            if (EPI == EPI_RELU || EPI == EPI_BIAS_RELU) {
                v0 = fmaxf(v0, 0.f); v1 = fmaxf(v1, 0.f);
                v2 = fmaxf(v2, 0.f); v3 = fmaxf(v3, 0.f);
            }
            *(float2*)&Cp[(long long)r * N + c] = make_float2(v0, v1);
            *(float2*)&Cp[(long long)(r + 8) * N + c] = make_float2(v2, v3);
        }
    }
}

// Row softmax over last axis + post-softmax triu mask (keep l <= m).
__global__ __launch_bounds__(256) void softmax_mask(float* __restrict__ P)
{
    const int L = L_DIM;
    const int l = blockIdx.x;
    float* row = P + ((long long)blockIdx.y * L + l) * L;
    const int t = threadIdx.x;

    float v[4];
    float m = -1e30f;
#pragma unroll
    for (int i = 0; i < 4; i++) {
        v[i] = row[t + 256 * i];
        m = fmaxf(m, v[i]);
    }

    __shared__ float red[8];
#pragma unroll
    for (int o = 16; o > 0; o >>= 1) m = fmaxf(m, __shfl_xor_sync(0xffffffffu, m, o));
    if ((t & 31) == 0) red[t >> 5] = m;
    __syncthreads();
    if (t < 32) {
        float x = (t < 8) ? red[t] : -1e30f;
#pragma unroll
        for (int o = 4; o > 0; o >>= 1) x = fmaxf(x, __shfl_xor_sync(0xffffffffu, x, o));
        if (t == 0) red[0] = x;
    }
    __syncthreads();
    m = red[0];

    float s = 0.f;
#pragma unroll
    for (int i = 0; i < 4; i++) {
        v[i] = expf(v[i] - m);
        s += v[i];
    }
    __syncthreads();
#pragma unroll
    for (int o = 16; o > 0; o >>= 1) s += __shfl_xor_sync(0xffffffffu, s, o);
    if ((t & 31) == 0) red[t >> 5] = s;
    __syncthreads();
    if (t < 32) {
        float x = (t < 8) ? red[t] : 0.f;
#pragma unroll
        for (int o = 4; o > 0; o >>= 1) x += __shfl_xor_sync(0xffffffffu, x, o);
        if (t == 0) red[0] = x;
    }
    __syncthreads();
    const float inv = 1.0f / red[0];

#pragma unroll
    for (int i = 0; i < 4; i++) {
        int c = t + 256 * i;
        row[c] = (l <= c) ? v[i] * inv : 0.f;
    }
}

extern "C" void kernel_launch(void* const* d_in, const int* in_sizes, int n_in,
                              void* d_out, int out_size)
{
    (void)in_sizes; (void)n_in; (void)out_size;
    const float* x  = (const float*)d_in[0];
    const float* Wq = (const float*)d_in[1];
    const float* bq = (const float*)d_in[2];
    const float* Wk = (const float*)d_in[3];
    const float* bk = (const float*)d_in[4];
    const float* Wv = (const float*)d_in[5];
    const float* bv = (const float*)d_in[6];
    const float* W1 = (const float*)d_in[7];
    const float* b1 = (const float*)d_in[8];
    const float* W2 = (const float*)d_in[9];
    const float* b2 = (const float*)d_in[10];
    float* out = (float*)d_out;

    float *q, *k, *v, *p, *h, *z;
    cudaGetSymbolAddress((void**)&q, g_q);
    cudaGetSymbolAddress((void**)&k, g_k);
    cudaGetSymbolAddress((void**)&v, g_v);
    cudaGetSymbolAddress((void**)&p, g_p);
    cudaGetSymbolAddress((void**)&h, g_h);
    cudaGetSymbolAddress((void**)&z, g_z);

    const long long AL = (long long)A_DIM * L_DIM;   // per-batch q/k/v/h/z stride
    const long long DL = (long long)D_DIM * L_DIM;   // per-head stride
    const long long PL = (long long)L_DIM * L_DIM;   // per-head P stride
    const long long XL = (long long)CIN_DIM * L_DIM; // per-batch x stride

    // 1) QKV projections: C[b] = W @ x[b] + bias ; M=2048, N=1024, K=512
    dim3 gproj(L_DIM / 128, A_DIM / 128, B_DIM);
    gemm_tc<128, false, EPI_BIAS><<<gproj, 256>>>(Wq, x, bq, q, A_DIM, L_DIM, CIN_DIM, 0, XL, AL);
    gemm_tc<128, false, EPI_BIAS><<<gproj, 256>>>(Wk, x, bk, k, A_DIM, L_DIM, CIN_DIM, 0, XL, AL);
    gemm_tc<128, false, EPI_BIAS><<<gproj, 256>>>(Wv, x, bv, v, A_DIM, L_DIM, CIN_DIM, 0, XL, AL);

    // 2) Scores per (b,h): S = q_h^T @ k_h (+rel bias, *1/8) ; M=N=1024, K=64
    dim3 gsc(L_DIM / 128, L_DIM / 128, B_DIM * H_DIM);
    gemm_tc<128, true, EPI_SCORES><<<gsc, 256>>>(q, k, nullptr, p, L_DIM, L_DIM, D_DIM, DL, DL, PL);

    // 3) Row softmax + post-softmax triu mask (in place on P)
    softmax_mask<<<dim3(L_DIM, B_DIM * H_DIM), 256>>>(p);

    // 4) Attn-out per (b,h): o = relu(v_h @ P) ; M=64, N=1024, K=1024
    dim3 gao(L_DIM / 128, 1, B_DIM * H_DIM);
    gemm_tc<64, false, EPI_RELU><<<gao, 256>>>(v, p, nullptr, h, D_DIM, L_DIM, L_DIM, DL, PL, DL);

    // 5) Final MLP: z = relu(W1 @ h + b1) ; out = W2 @ z + b2 ; M=2048, N=1024, K=2048
    dim3 gf(L_DIM / 128, A_DIM / 128, B_DIM);
    gemm_tc<128, false, EPI_BIAS_RELU><<<gf, 256>>>(W1, h, b1, z, A_DIM, L_DIM, A_DIM, 0, AL, AL);
    gemm_tc<128, false, EPI_BIAS><<<gf, 256>>>(W2, z, b2, out, A_DIM, L_DIM, A_DIM, 0, AL, AL);
}

// round 3
// speedup vs baseline: 2.6336x; 1.1369x over previous
#include <cuda_runtime.h>
#include <cstdint>
#include <math.h>

// Problem constants
#define B_DIM 2
#define CIN_DIM 512
#define L_DIM 1024
#define H_DIM 32
#define D_DIM 64
#define A_DIM 2048   // H*D
#define BH_DIM (B_DIM * H_DIM)

// Scratch (static device arrays; allocation-free per harness rules)
__device__ float g_q[B_DIM * A_DIM * L_DIM];   // 16 MB
__device__ float g_k[B_DIM * A_DIM * L_DIM];   // 16 MB
__device__ float g_v[B_DIM * A_DIM * L_DIM];   // 16 MB
__device__ float g_h[B_DIM * A_DIM * L_DIM];   // 16 MB
__device__ float g_z[B_DIM * A_DIM * L_DIM];   // 16 MB
__device__ float g_mx[BH_DIM * L_DIM];         // row max
__device__ float g_is[BH_DIM * L_DIM];         // 1 / row sum

enum { EPI_NONE = 0, EPI_BIAS = 1, EPI_BIAS_RELU = 2, EPI_RELU = 3 };

__device__ __forceinline__ float cvt_tf32(float x) {
    uint32_t u;
    asm("cvt.rna.tf32.f32 %0, %1;" : "=r"(u) : "f"(x));
    return __uint_as_float(u);
}

__device__ __forceinline__ void mma_tf32(float c[4], const uint32_t a[4], const uint32_t b[2]) {
    asm volatile(
        "mma.sync.aligned.m16n8k8.row.col.f32.tf32.tf32.f32 "
        "{%0,%1,%2,%3}, {%4,%5,%6,%7}, {%8,%9}, {%0,%1,%2,%3};\n"
        : "+f"(c[0]), "+f"(c[1]), "+f"(c[2]), "+f"(c[3])
        : "r"(a[0]), "r"(a[1]), "r"(a[2]), "r"(a[3]), "r"(b[0]), "r"(b[1]));
}

// ============================================================================
// Batched TF32 tensor-core GEMM (projections + MLP): C[z] = A[z] @ B[z] (+epi)
// A row-major [M,K], B row-major [K,N], C row-major [M,N].
// Requires: M % 128 == 0, N % 128 == 0, K % 16 == 0.
// ============================================================================
template <int EPI>
__global__ __launch_bounds__(256) void gemm_tc(
    const float* __restrict__ Ag, const float* __restrict__ Bg,
    const float* __restrict__ bias, float* __restrict__ Cg,
    int M, int N, int K,
    long long Abs, long long Bbs, long long Cbs)
{
    constexpr int BM = 128, BN = 128, KC = 16;
    constexpr int ASTR = BM + 8;
    constexpr int BSTR = BN + 8;

    __shared__ float As[2][KC * ASTR];
    __shared__ float Bs[2][KC * BSTR];

    const float* Ap = Ag + (long long)blockIdx.z * Abs;
    const float* Bp = Bg + (long long)blockIdx.z * Bbs;
    float* Cp = Cg + (long long)blockIdx.z * Cbs;

    const int tid = threadIdx.x;
    const int lane = tid & 31;
    const int w = tid >> 5;
    const int wm = w & 3, wn = w >> 2;   // 4 x 2 warps
    const int row0 = blockIdx.y * BM;
    const int col0 = blockIdx.x * BN;

    float acc[2][8][4] = {};
    float4 pa[2], pb[2];

    auto fetch = [&](int k0) {
#pragma unroll
        for (int u = 0; u < 2; ++u) {
            int idx = tid + u * 256;
            int r = idx % BM, j = idx / BM;
            pa[u] = *(const float4*)&Ap[(long long)(row0 + r) * K + k0 + 4 * j];
        }
#pragma unroll
        for (int u = 0; u < 2; ++u) {
            int idx = tid + u * 256;
            int nq = idx % (BN / 4), kk = idx / (BN / 4);
            pb[u] = *(const float4*)&Bp[(long long)(k0 + kk) * N + col0 + 4 * nq];
        }
    };

    auto stage = [&](int buf) {
#pragma unroll
        for (int u = 0; u < 2; ++u) {
            int idx = tid + u * 256;
            int r = idx % BM, j = idx / BM;
            As[buf][(4 * j + 0) * ASTR + r] = cvt_tf32(pa[u].x);
            As[buf][(4 * j + 1) * ASTR + r] = cvt_tf32(pa[u].y);
            As[buf][(4 * j + 2) * ASTR + r] = cvt_tf32(pa[u].z);
            As[buf][(4 * j + 3) * ASTR + r] = cvt_tf32(pa[u].w);
        }
#pragma unroll
        for (int u = 0; u < 2; ++u) {
            int idx = tid + u * 256;
            int nq = idx % (BN / 4), kk = idx / (BN / 4);
            float4 t;
            t.x = cvt_tf32(pb[u].x); t.y = cvt_tf32(pb[u].y);
            t.z = cvt_tf32(pb[u].z); t.w = cvt_tf32(pb[u].w);
            *(float4*)&Bs[buf][kk * BSTR + 4 * nq] = t;
        }
    };

    auto compute = [&](int buf) {
        const int row = lane >> 2, kcol = lane & 3;
#pragma unroll
        for (int ks = 0; ks < KC; ks += 8) {
            uint32_t af[2][4];
#pragma unroll
            for (int f = 0; f < 2; ++f) {
                const float* Ab = &As[buf][(ks + kcol) * ASTR + wm * 32 + f * 16 + row];
                af[f][0] = __float_as_uint(Ab[0]);
                af[f][1] = __float_as_uint(Ab[8]);
                af[f][2] = __float_as_uint(Ab[4 * ASTR]);
                af[f][3] = __float_as_uint(Ab[4 * ASTR + 8]);
            }
            uint32_t bf[8][2];
#pragma unroll
            for (int g = 0; g < 8; ++g) {
                const float* Bb = &Bs[buf][(ks + kcol) * BSTR + wn * 64 + g * 8 + row];
                bf[g][0] = __float_as_uint(Bb[0]);
                bf[g][1] = __float_as_uint(Bb[4 * BSTR]);
            }
#pragma unroll
            for (int f = 0; f < 2; ++f)
#pragma unroll
                for (int g = 0; g < 8; ++g)
                    mma_tf32(acc[f][g], af[f], bf[g]);
        }
    };

    const int nit = K / KC;
    fetch(0);
    stage(0);
    __syncthreads();
    for (int it = 0; it < nit; ++it) {
        int cur = it & 1;
        if (it + 1 < nit) fetch((it + 1) * KC);
        compute(cur);
        if (it + 1 < nit) {
            stage(cur ^ 1);
            __syncthreads();
        }
    }

#pragma unroll
    for (int f = 0; f < 2; ++f) {
        int r = row0 + wm * 32 + f * 16 + (lane >> 2);
        float b0v = 0.f, b8v = 0.f;
        if (EPI == EPI_BIAS || EPI == EPI_BIAS_RELU) { b0v = bias[r]; b8v = bias[r + 8]; }
#pragma unroll
        for (int g = 0; g < 8; ++g) {
            int c = col0 + wn * 64 + g * 8 + (lane & 3) * 2;
            float v0 = acc[f][g][0] + b0v;
            float v1 = acc[f][g][1] + b0v;
            float v2 = acc[f][g][2] + b8v;
            float v3 = acc[f][g][3] + b8v;
            if (EPI == EPI_RELU || EPI == EPI_BIAS_RELU) {
                v0 = fmaxf(v0, 0.f); v1 = fmaxf(v1, 0.f);
                v2 = fmaxf(v2, 0.f); v3 = fmaxf(v3, 0.f);
            }
            *(float2*)&Cp[(long long)r * N + c] = make_float2(v0, v1);
            *(float2*)&Cp[(long long)(r + 8) * N + c] = make_float2(v2, v3);
        }
    }
}

// ============================================================================
// Attention pass 1: per (bh, l-tile) compute softmax row stats (max, 1/sum)
// over the full biased score row. q,k stored [bh][d=64][l=1024].
// grid (8, BH), 256 threads, dyn smem = 2 * 64*136 floats.
// ============================================================================
__global__ __launch_bounds__(256) void attn_stats(
    const float* __restrict__ q, const float* __restrict__ k,
    float* __restrict__ gM, float* __restrict__ gIS)
{
    extern __shared__ float smem[];
    float* Qs = smem;              // [64][136]
    float* Ks = smem + 64 * 136;   // [64][136]

    const long long DL = (long long)D_DIM * L_DIM;
    const int bh = blockIdx.y;
    const int l0 = blockIdx.x * 128;
    const float* qh = q + (long long)bh * DL;
    const float* kh = k + (long long)bh * DL;
    const int tid = threadIdx.x, lane = tid & 31, w = tid >> 5;
    const int wm = w & 3, wn = w >> 2;   // 4 x 2
    const int row = lane >> 2, kq = lane & 3;

    // stage Q tile [d=64][l=128] (k-major layout already)
#pragma unroll
    for (int u = 0; u < 8; ++u) {
        int idx = tid + u * 256;
        int d = idx >> 5, cq = (idx & 31) * 4;
        float4 t = *(const float4*)&qh[(long long)d * L_DIM + l0 + cq];
        t.x = cvt_tf32(t.x); t.y = cvt_tf32(t.y);
        t.z = cvt_tf32(t.z); t.w = cvt_tf32(t.w);
        *(float4*)&Qs[d * 136 + cq] = t;
    }

    float Mx[4] = { -1e30f, -1e30f, -1e30f, -1e30f };
    float Sm[4] = { 0.f, 0.f, 0.f, 0.f };

    for (int mt = 0; mt < 8; ++mt) {
        __syncthreads();
#pragma unroll
        for (int u = 0; u < 8; ++u) {
            int idx = tid + u * 256;
            int d = idx >> 5, cq = (idx & 31) * 4;
            float4 t = *(const float4*)&kh[(long long)d * L_DIM + mt * 128 + cq];
            t.x = cvt_tf32(t.x); t.y = cvt_tf32(t.y);
            t.z = cvt_tf32(t.z); t.w = cvt_tf32(t.w);
            *(float4*)&Ks[d * 136 + cq] = t;
        }
        __syncthreads();

        float acc[2][8][4] = {};
#pragma unroll
        for (int ks = 0; ks < 64; ks += 8) {
            uint32_t af[2][4];
#pragma unroll
            for (int f = 0; f < 2; ++f) {
                const float* Ab = &Qs[(ks + kq) * 136 + wm * 32 + f * 16 + row];
                af[f][0] = __float_as_uint(Ab[0]);
                af[f][1] = __float_as_uint(Ab[8]);
                af[f][2] = __float_as_uint(Ab[4 * 136]);
                af[f][3] = __float_as_uint(Ab[4 * 136 + 8]);
            }
            uint32_t bf[8][2];
#pragma unroll
            for (int g = 0; g < 8; ++g) {
                const float* Bb = &Ks[(ks + kq) * 136 + wn * 64 + g * 8 + row];
                bf[g][0] = __float_as_uint(Bb[0]);
                bf[g][1] = __float_as_uint(Bb[4 * 136]);
            }
#pragma unroll
            for (int f = 0; f < 2; ++f)
#pragma unroll
                for (int g = 0; g < 8; ++g)
                    mma_tf32(acc[f][g], af[f], bf[g]);
        }

        // online stats update (tile max then one merge -> ~1.1 exp / element)
#pragma unroll
        for (int f = 0; f < 2; ++f)
#pragma unroll
            for (int sub = 0; sub < 2; ++sub) {
                int lr = l0 + wm * 32 + f * 16 + sub * 8 + row;
                float xv[16];
                float tm = -1e30f;
#pragma unroll
                for (int g = 0; g < 8; ++g) {
                    int m = mt * 128 + wn * 64 + g * 8 + kq * 2;
                    float x0 = (acc[f][g][2 * sub]     - fabsf((float)(lr - m)))     * 0.125f;
                    float x1 = (acc[f][g][2 * sub + 1] - fabsf((float)(lr - m - 1))) * 0.125f;
                    xv[2 * g] = x0; xv[2 * g + 1] = x1;
                    tm = fmaxf(tm, fmaxf(x0, x1));
                }
                float ts = 0.f;
#pragma unroll
                for (int i2 = 0; i2 < 16; ++i2) ts += __expf(xv[i2] - tm);
                int i = 2 * f + sub;
                float nm = fmaxf(Mx[i], tm);
                Sm[i] = Sm[i] * __expf(Mx[i] - nm) + ts * __expf(tm - nm);
                Mx[i] = nm;
            }
    }

    // merge across the 4 lanes sharing each row
#pragma unroll
    for (int i = 0; i < 4; ++i) {
#pragma unroll
        for (int o = 1; o <= 2; o <<= 1) {
            float oM = __shfl_xor_sync(0xffffffffu, Mx[i], o);
            float oS = __shfl_xor_sync(0xffffffffu, Sm[i], o);
            float nm = fmaxf(Mx[i], oM);
            Sm[i] = Sm[i] * __expf(Mx[i] - nm) + oS * __expf(oM - nm);
            Mx[i] = nm;
        }
    }
    __syncthreads();
    float* sM = Qs;          // scratch reuse: [2][128]
    float* sS = Qs + 256;
    if (kq == 0) {
#pragma unroll
        for (int f = 0; f < 2; ++f)
#pragma unroll
            for (int sub = 0; sub < 2; ++sub) {
                int rl = wm * 32 + f * 16 + sub * 8 + row;
                sM[wn * 128 + rl] = Mx[2 * f + sub];
                sS[wn * 128 + rl] = Sm[2 * f + sub];
            }
    }
    __syncthreads();
    if (tid < 128) {
        float M0 = sM[tid], M1 = sM[128 + tid];
        float S0 = sS[tid], S1 = sS[128 + tid];
        float nm = fmaxf(M0, M1);
        float S = S0 * __expf(M0 - nm) + S1 * __expf(M1 - nm);
        gM[bh * L_DIM + l0 + tid] = nm;
        gIS[bh * L_DIM + l0 + tid] = 1.0f / S;
    }
}

// ============================================================================
// Attention pass 2: per (bh, m-tile) recompute S tiles, apply softmax weights
// + triu mask, accumulate O[64 x 128] = V @ W, fused ReLU -> h.
// grid (8, BH) with mb = 7 - blockIdx.x (heavy blocks first), 256 threads.
// dyn smem = 64*136*2 + 128*72 + 128*136 floats.
// ============================================================================
__global__ __launch_bounds__(256) void attn_out(
    const float* __restrict__ q, const float* __restrict__ k,
    const float* __restrict__ v, const float* __restrict__ gM,
    const float* __restrict__ gIS, float* __restrict__ hout)
{
    extern __shared__ float smem[];
    float* Qs = smem;                   // [64][136]
    float* Ks = Qs + 64 * 136;          // [64][136]
    float* Vs = Ks + 64 * 136;          // [128][72]  (l-major, d contiguous rows)
    float* Ws = Vs + 128 * 72;          // [128][136]

    const long long DL = (long long)D_DIM * L_DIM;
    const int bh = blockIdx.y;
    const int mb = (int)(gridDim.x - 1 - blockIdx.x);
    const int m0 = mb * 128;
    const float* qh = q + (long long)bh * DL;
    const float* kh = k + (long long)bh * DL;
    const float* vh = v + (long long)bh * DL;
    const int tid = threadIdx.x, lane = tid & 31, w = tid >> 5;
    const int wm = w & 3,  wn = w >> 2;    // S-MMA layout: 4 x 2
    const int wm2 = w & 1, wn2 = w >> 1;   // O-MMA layout: 2 x 4
    const int row = lane >> 2, kq = lane & 3;

    // stage K tile once: k[d][m0..m0+127]
#pragma unroll
    for (int u = 0; u < 8; ++u) {
        int idx = tid + u * 256;
        int d = idx >> 5, cq = (idx & 31) * 4;
        float4 t = *(const float4*)&kh[(long long)d * L_DIM + m0 + cq];
        t.x = cvt_tf32(t.x); t.y = cvt_tf32(t.y);
        t.z = cvt_tf32(t.z); t.w = cvt_tf32(t.w);
        *(float4*)&Ks[d * 136 + cq] = t;
    }

    float accO[2][4][4] = {};

    for (int lb = 0; lb <= mb; ++lb) {
        __syncthreads();   // previous iteration's reads of Qs/Vs/Ws complete
        // stage Q tile
#pragma unroll
        for (int u = 0; u < 8; ++u) {
            int idx = tid + u * 256;
            int d = idx >> 5, cq = (idx & 31) * 4;
            float4 t = *(const float4*)&qh[(long long)d * L_DIM + lb * 128 + cq];
            t.x = cvt_tf32(t.x); t.y = cvt_tf32(t.y);
            t.z = cvt_tf32(t.z); t.w = cvt_tf32(t.w);
            *(float4*)&Qs[d * 136 + cq] = t;
        }
        // stage V tile transposed: Vs[l][d]
#pragma unroll
        for (int u = 0; u < 8; ++u) {
            int idx = tid + u * 256;
            int d = idx & 63, lq = idx >> 6;
            float4 t = *(const float4*)&vh[(long long)d * L_DIM + lb * 128 + 4 * lq];
            Vs[(4 * lq + 0) * 72 + d] = cvt_tf32(t.x);
            Vs[(4 * lq + 1) * 72 + d] = cvt_tf32(t.y);
            Vs[(4 * lq + 2) * 72 + d] = cvt_tf32(t.z);
            Vs[(4 * lq + 3) * 72 + d] = cvt_tf32(t.w);
        }
        __syncthreads();

        // S = Q^T K tile [l=128][m=128]
        float acc[2][8][4] = {};
#pragma unroll
        for (int ks = 0; ks < 64; ks += 8) {
            uint32_t af[2][4];
#pragma unroll
            for (int f = 0; f < 2; ++f) {
                const float* Ab = &Qs[(ks + kq) * 136 + wm * 32 + f * 16 + row];
                af[f][0] = __float_as_uint(Ab[0]);
                af[f][1] = __float_as_uint(Ab[8]);
                af[f][2] = __float_as_uint(Ab[4 * 136]);
                af[f][3] = __float_as_uint(Ab[4 * 136 + 8]);
            }
            uint32_t bf[8][2];
#pragma unroll
            for (int g = 0; g < 8; ++g) {
                const float* Bb = &Ks[(ks + kq) * 136 + wn * 64 + g * 8 + row];
                bf[g][0] = __float_as_uint(Bb[0]);
                bf[g][1] = __float_as_uint(Bb[4 * 136]);
            }
#pragma unroll
            for (int f = 0; f < 2; ++f)
#pragma unroll
                for (int g = 0; g < 8; ++g)
                    mma_tf32(acc[f][g], af[f], bf[g]);
        }

        // softmax weights + triu mask -> Ws (tf32)
#pragma unroll
        for (int f = 0; f < 2; ++f)
#pragma unroll
            for (int sub = 0; sub < 2; ++sub) {
                int lloc = wm * 32 + f * 16 + sub * 8 + row;
                int lg = lb * 128 + lloc;
                float Mrow = gM[bh * L_DIM + lg];
                float IS = gIS[bh * L_DIM + lg];
#pragma unroll
                for (int g = 0; g < 8; ++g) {
                    int c = wn * 64 + g * 8 + kq * 2;
                    int mg = m0 + c;
                    float x0 = (acc[f][g][2 * sub]     - fabsf((float)(lg - mg)))     * 0.125f;
                    float x1 = (acc[f][g][2 * sub + 1] - fabsf((float)(lg - mg - 1))) * 0.125f;
                    float w0 = __expf(x0 - Mrow) * IS;
                    float w1 = __expf(x1 - Mrow) * IS;
                    if (lb == mb) {
                        if (lg > mg)     w0 = 0.f;
                        if (lg > mg + 1) w1 = 0.f;
                    }
                    float2 t2;
                    t2.x = cvt_tf32(w0);
                    t2.y = cvt_tf32(w1);
                    *(float2*)&Ws[lloc * 136 + c] = t2;
                }
            }
        __syncthreads();

        // O += V[d=64 x l=128] @ W[l=128 x m=128]
#pragma unroll
        for (int ks = 0; ks < 128; ks += 8) {
            uint32_t af[2][4];
#pragma unroll
            for (int f = 0; f < 2; ++f) {
                const float* Ab = &Vs[(ks + kq) * 72 + wm2 * 32 + f * 16 + row];
                af[f][0] = __float_as_uint(Ab[0]);
                af[f][1] = __float_as_uint(Ab[8]);
                af[f][2] = __float_as_uint(Ab[4 * 72]);
                af[f][3] = __float_as_uint(Ab[4 * 72 + 8]);
            }
            uint32_t bfr[4][2];
#pragma unroll
            for (int g = 0; g < 4; ++g) {
                const float* Bb = &Ws[(ks + kq) * 136 + wn2 * 32 + g * 8 + row];
                bfr[g][0] = __float_as_uint(Bb[0]);
                bfr[g][1] = __float_as_uint(Bb[4 * 136]);
            }
#pragma unroll
            for (int f = 0; f < 2; ++f)
#pragma unroll
                for (int g = 0; g < 4; ++g)
                    mma_tf32(accO[f][g], af[f], bfr[g]);
        }
    }

    // epilogue: ReLU, store h[d][m]
#pragma unroll
    for (int f = 0; f < 2; ++f) {
        int rd = wm2 * 32 + f * 16 + row;
#pragma unroll
        for (int g = 0; g < 4; ++g) {
            int cm = m0 + wn2 * 32 + g * 8 + kq * 2;
            float2 a = make_float2(fmaxf(accO[f][g][0], 0.f), fmaxf(accO[f][g][1], 0.f));
            float2 b = make_float2(fmaxf(accO[f][g][2], 0.f), fmaxf(accO[f][g][3], 0.f));
            *(float2*)&hout[(long long)bh * DL + (long long)rd * L_DIM + cm] = a;
            *(float2*)&hout[(long long)bh * DL + (long long)(rd + 8) * L_DIM + cm] = b;
        }
    }
}

// ============================================================================
extern "C" void kernel_launch(void* const* d_in, const int* in_sizes, int n_in,
                              void* d_out, int out_size)
{
    (void)in_sizes; (void)n_in; (void)out_size;
    const float* x  = (const float*)d_in[0];
    const float* Wq = (const float*)d_in[1];
    const float* bq = (const float*)d_in[2];
    const float* Wk = (const float*)d_in[3];
    const float* bk = (const float*)d_in[4];
    const float* Wv = (const float*)d_in[5];
    const float* bv = (const float*)d_in[6];
    const float* W1 = (const float*)d_in[7];
    const float* b1 = (const float*)d_in[8];
    const float* W2 = (const float*)d_in[9];
    const float* b2 = (const float*)d_in[10];
    float* out = (float*)d_out;

    float *q, *k, *v, *h, *z, *mx, *is;
    cudaGetSymbolAddress((void**)&q, g_q);
    cudaGetSymbolAddress((void**)&k, g_k);
    cudaGetSymbolAddress((void**)&v, g_v);
    cudaGetSymbolAddress((void**)&h, g_h);
    cudaGetSymbolAddress((void**)&z, g_z);
    cudaGetSymbolAddress((void**)&mx, g_mx);
    cudaGetSymbolAddress((void**)&is, g_is);

    const long long AL = (long long)A_DIM * L_DIM;
    const long long XL = (long long)CIN_DIM * L_DIM;

    const int SMEM1 = (64 * 136 * 2) * 4;                           // 69632 B
    const int SMEM2 = (64 * 136 * 2 + 128 * 72 + 128 * 136) * 4;    // 176128 B
    cudaFuncSetAttribute(attn_stats, cudaFuncAttributeMaxDynamicSharedMemorySize, SMEM1);
    cudaFuncSetAttribute(attn_out,   cudaFuncAttributeMaxDynamicSharedMemorySize, SMEM2);

    // 1) QKV projections
    dim3 gproj(L_DIM / 128, A_DIM / 128, B_DIM);
    gemm_tc<EPI_BIAS><<<gproj, 256>>>(Wq, x, bq, q, A_DIM, L_DIM, CIN_DIM, 0, XL, AL);
    gemm_tc<EPI_BIAS><<<gproj, 256>>>(Wk, x, bk, k, A_DIM, L_DIM, CIN_DIM, 0, XL, AL);
    gemm_tc<EPI_BIAS><<<gproj, 256>>>(Wv, x, bv, v, A_DIM, L_DIM, CIN_DIM, 0, XL, AL);

    // 2) Fused attention (no materialized P)
    attn_stats<<<dim3(8, BH_DIM), 256, SMEM1>>>(q, k, mx, is);
    attn_out<<<dim3(8, BH_DIM), 256, SMEM2>>>(q, k, v, mx, is, h);

    // 3) Final MLP
    dim3 gf(L_DIM / 128, A_DIM / 128, B_DIM);
    gemm_tc<EPI_BIAS_RELU><<<gf, 256>>>(W1, h, b1, z, A_DIM, L_DIM, A_DIM, 0, AL, AL);
    gemm_tc<EPI_BIAS><<<gf, 256>>>(W2, z, b2, out, A_DIM, L_DIM, A_DIM, 0, AL, AL);
}

// round 5
// speedup vs baseline: 2.6655x; 1.0121x over previous
#include <cuda_runtime.h>
#include <cstdint>
#include <math.h>

// Problem constants
#define B_DIM 2
#define CIN_DIM 512
#define L_DIM 1024
#define H_DIM 32
#define D_DIM 64
#define A_DIM 2048   // H*D
#define BH_DIM (B_DIM * H_DIM)

// Scratch
__device__ float g_q[B_DIM * A_DIM * L_DIM];
__device__ float g_k[B_DIM * A_DIM * L_DIM];
__device__ float g_v[B_DIM * A_DIM * L_DIM];
__device__ float g_h[B_DIM * A_DIM * L_DIM];
__device__ float g_z[B_DIM * A_DIM * L_DIM];
__device__ float g_mx[BH_DIM * L_DIM];
__device__ float g_is[BH_DIM * L_DIM];

enum { EPI_NONE = 0, EPI_BIAS = 1, EPI_BIAS_RELU = 2, EPI_RELU = 3 };

__device__ __forceinline__ float cvt_tf32(float x) {
    uint32_t u;
    asm("cvt.rna.tf32.f32 %0, %1;" : "=r"(u) : "f"(x));
    return __uint_as_float(u);
}
__device__ __forceinline__ uint32_t cvt_tf32_u(float x) {
    uint32_t u;
    asm("cvt.rna.tf32.f32 %0, %1;" : "=r"(u) : "f"(x));
    return u;
}

__device__ __forceinline__ void mma_tf32(float c[4], const uint32_t a[4], const uint32_t b[2]) {
    asm volatile(
        "mma.sync.aligned.m16n8k8.row.col.f32.tf32.tf32.f32 "
        "{%0,%1,%2,%3}, {%4,%5,%6,%7}, {%8,%9}, {%0,%1,%2,%3};\n"
        : "+f"(c[0]), "+f"(c[1]), "+f"(c[2]), "+f"(c[3])
        : "r"(a[0]), "r"(a[1]), "r"(a[2]), "r"(a[3]), "r"(b[0]), "r"(b[1]));
}

__device__ __forceinline__ void cp_async16(float* sptr, const float* gptr) {
    uint32_t s = (uint32_t)__cvta_generic_to_shared(sptr);
    asm volatile("cp.async.cg.shared.global [%0], [%1], 16;\n" :: "r"(s), "l"(gptr));
}
__device__ __forceinline__ void cp_commit() { asm volatile("cp.async.commit_group;\n"); }
__device__ __forceinline__ void cp_wait0() { asm volatile("cp.async.wait_group 0;\n"); }
__device__ __forceinline__ void cp_wait1() { asm volatile("cp.async.wait_group 1;\n"); }

// ============================================================================
// Batched TF32 GEMM (projections + MLP) — unchanged (passing since round 2)
// ============================================================================
template <int EPI>
__global__ __launch_bounds__(256) void gemm_tc(
    const float* __restrict__ Ag, const float* __restrict__ Bg,
    const float* __restrict__ bias, float* __restrict__ Cg,
    int M, int N, int K,
    long long Abs, long long Bbs, long long Cbs)
{
    constexpr int BM = 128, BN = 128, KC = 16;
    constexpr int ASTR = BM + 8;
    constexpr int BSTR = BN + 8;

    __shared__ float As[2][KC * ASTR];
    __shared__ float Bs[2][KC * BSTR];

    const float* Ap = Ag + (long long)blockIdx.z * Abs;
    const float* Bp = Bg + (long long)blockIdx.z * Bbs;
    float* Cp = Cg + (long long)blockIdx.z * Cbs;

    const int tid = threadIdx.x;
    const int lane = tid & 31;
    const int w = tid >> 5;
    const int wm = w & 3, wn = w >> 2;
    const int row0 = blockIdx.y * BM;
    const int col0 = blockIdx.x * BN;

    float acc[2][8][4] = {};
    float4 pa[2], pb[2];

    auto fetch = [&](int k0) {
#pragma unroll
        for (int u = 0; u < 2; ++u) {
            int idx = tid + u * 256;
            int r = idx % BM, j = idx / BM;
            pa[u] = *(const float4*)&Ap[(long long)(row0 + r) * K + k0 + 4 * j];
        }
#pragma unroll
        for (int u = 0; u < 2; ++u) {
            int idx = tid + u * 256;
            int nq = idx % (BN / 4), kk = idx / (BN / 4);
            pb[u] = *(const float4*)&Bp[(long long)(k0 + kk) * N + col0 + 4 * nq];
        }
    };

    auto stage = [&](int buf) {
#pragma unroll
        for (int u = 0; u < 2; ++u) {
            int idx = tid + u * 256;
            int r = idx % BM, j = idx / BM;
            As[buf][(4 * j + 0) * ASTR + r] = cvt_tf32(pa[u].x);
            As[buf][(4 * j + 1) * ASTR + r] = cvt_tf32(pa[u].y);
            As[buf][(4 * j + 2) * ASTR + r] = cvt_tf32(pa[u].z);
            As[buf][(4 * j + 3) * ASTR + r] = cvt_tf32(pa[u].w);
        }
#pragma unroll
        for (int u = 0; u < 2; ++u) {
            int idx = tid + u * 256;
            int nq = idx % (BN / 4), kk = idx / (BN / 4);
            float4 t;
            t.x = cvt_tf32(pb[u].x); t.y = cvt_tf32(pb[u].y);
            t.z = cvt_tf32(pb[u].z); t.w = cvt_tf32(pb[u].w);
            *(float4*)&Bs[buf][kk * BSTR + 4 * nq] = t;
        }
    };

    auto compute = [&](int buf) {
        const int row = lane >> 2, kcol = lane & 3;
#pragma unroll
        for (int ks = 0; ks < KC; ks += 8) {
            uint32_t af[2][4];
#pragma unroll
            for (int f = 0; f < 2; ++f) {
                const float* Ab = &As[buf][(ks + kcol) * ASTR + wm * 32 + f * 16 + row];
                af[f][0] = __float_as_uint(Ab[0]);
                af[f][1] = __float_as_uint(Ab[8]);
                af[f][2] = __float_as_uint(Ab[4 * ASTR]);
                af[f][3] = __float_as_uint(Ab[4 * ASTR + 8]);
            }
            uint32_t bf[8][2];
#pragma unroll
            for (int g = 0; g < 8; ++g) {
                const float* Bb = &Bs[buf][(ks + kcol) * BSTR + wn * 64 + g * 8 + row];
                bf[g][0] = __float_as_uint(Bb[0]);
                bf[g][1] = __float_as_uint(Bb[4 * BSTR]);
            }
#pragma unroll
            for (int f = 0; f < 2; ++f)
#pragma unroll
                for (int g = 0; g < 8; ++g)
                    mma_tf32(acc[f][g], af[f], bf[g]);
        }
    };

    const int nit = K / KC;
    fetch(0);
    stage(0);
    __syncthreads();
    for (int it = 0; it < nit; ++it) {
        int cur = it & 1;
        if (it + 1 < nit) fetch((it + 1) * KC);
        compute(cur);
        if (it + 1 < nit) {
            stage(cur ^ 1);
            __syncthreads();
        }
    }

#pragma unroll
    for (int f = 0; f < 2; ++f) {
        int r = row0 + wm * 32 + f * 16 + (lane >> 2);
        float b0v = 0.f, b8v = 0.f;
        if (EPI == EPI_BIAS || EPI == EPI_BIAS_RELU) { b0v = bias[r]; b8v = bias[r + 8]; }
#pragma unroll
        for (int g = 0; g < 8; ++g) {
            int c = col0 + wn * 64 + g * 8 + (lane & 3) * 2;
            float v0 = acc[f][g][0] + b0v;
            float v1 = acc[f][g][1] + b0v;
            float v2 = acc[f][g][2] + b8v;
            float v3 = acc[f][g][3] + b8v;
            if (EPI == EPI_RELU || EPI == EPI_BIAS_RELU) {
                v0 = fmaxf(v0, 0.f); v1 = fmaxf(v1, 0.f);
                v2 = fmaxf(v2, 0.f); v3 = fmaxf(v3, 0.f);
            }
            *(float2*)&Cp[(long long)r * N + c] = make_float2(v0, v1);
            *(float2*)&Cp[(long long)(r + 8) * N + c] = make_float2(v2, v3);
        }
    }
}

// ============================================================================
// Attention pass 1: softmax row stats. Q tile persistent (tf32, stride 136),
// K tiles double-buffered raw f32 via cp.async (cvt at fragment read).
// 64x128 tile = 8192 floats -> 8 float4 per thread (u < 8).
// smem = (64*136)*3 floats = 104448 B -> 2 CTAs/SM.
// ============================================================================
__global__ __launch_bounds__(256, 2) void attn_stats(
    const float* __restrict__ q, const float* __restrict__ k,
    float* __restrict__ gM, float* __restrict__ gIS)
{
    extern __shared__ float smem[];
    float* Qs = smem;                    // [64][136] tf32
    float* Kb[2] = { smem + 64 * 136, smem + 2 * 64 * 136 };  // raw

    const long long DL = (long long)D_DIM * L_DIM;
    const int bh = blockIdx.y;
    const int l0 = blockIdx.x * 128;
    const float* qh = q + (long long)bh * DL;
    const float* kh = k + (long long)bh * DL;
    const int tid = threadIdx.x, lane = tid & 31, w = tid >> 5;
    const int wm = w & 3, wn = w >> 2;
    const int row = lane >> 2, kq = lane & 3;

    // prefetch K(0): full 64x128 tile
#pragma unroll
    for (int u = 0; u < 8; ++u) {
        int idx = tid + u * 256;
        int d = idx >> 5, c = (idx & 31) * 4;
        cp_async16(&Kb[0][d * 136 + c], &kh[(long long)d * L_DIM + c]);
    }
    cp_commit();

    // stage Q tile (tf32), full 64x128
#pragma unroll
    for (int u = 0; u < 8; ++u) {
        int idx = tid + u * 256;
        int d = idx >> 5, c = (idx & 31) * 4;
        float4 t = *(const float4*)&qh[(long long)d * L_DIM + l0 + c];
        t.x = cvt_tf32(t.x); t.y = cvt_tf32(t.y);
        t.z = cvt_tf32(t.z); t.w = cvt_tf32(t.w);
        *(float4*)&Qs[d * 136 + c] = t;
    }

    float Mx[4] = { -1e30f, -1e30f, -1e30f, -1e30f };
    float Sm[4] = { 0.f, 0.f, 0.f, 0.f };

    for (int mt = 0; mt < 8; ++mt) {
        const float* Ks = Kb[mt & 1];
        cp_wait0();
        __syncthreads();
        if (mt < 7) {
            float* Kn = Kb[(mt & 1) ^ 1];
#pragma unroll
            for (int u = 0; u < 8; ++u) {
                int idx = tid + u * 256;
                int d = idx >> 5, c = (idx & 31) * 4;
                cp_async16(&Kn[d * 136 + c], &kh[(long long)d * L_DIM + (mt + 1) * 128 + c]);
            }
            cp_commit();
        }

        float acc[2][8][4] = {};
#pragma unroll
        for (int ks = 0; ks < 64; ks += 8) {
            uint32_t af[2][4];
#pragma unroll
            for (int f = 0; f < 2; ++f) {
                const float* Ab = &Qs[(ks + kq) * 136 + wm * 32 + f * 16 + row];
                af[f][0] = __float_as_uint(Ab[0]);
                af[f][1] = __float_as_uint(Ab[8]);
                af[f][2] = __float_as_uint(Ab[4 * 136]);
                af[f][3] = __float_as_uint(Ab[4 * 136 + 8]);
            }
            uint32_t bf[8][2];
#pragma unroll
            for (int g = 0; g < 8; ++g) {
                const float* Bb = &Ks[(ks + kq) * 136 + wn * 64 + g * 8 + row];
                bf[g][0] = cvt_tf32_u(Bb[0]);
                bf[g][1] = cvt_tf32_u(Bb[4 * 136]);
            }
#pragma unroll
            for (int f = 0; f < 2; ++f)
#pragma unroll
                for (int g = 0; g < 8; ++g)
                    mma_tf32(acc[f][g], af[f], bf[g]);
        }

        // online stats (recompute x in 2nd pass; no xv[] array -> lower regs)
#pragma unroll
        for (int f = 0; f < 2; ++f)
#pragma unroll
            for (int sub = 0; sub < 2; ++sub) {
                int lr = l0 + wm * 32 + f * 16 + sub * 8 + row;
                float tm = -1e30f;
#pragma unroll
                for (int g = 0; g < 8; ++g) {
                    int m = mt * 128 + wn * 64 + g * 8 + kq * 2;
                    float x0 = (acc[f][g][2 * sub]     - fabsf((float)(lr - m)))     * 0.125f;
                    float x1 = (acc[f][g][2 * sub + 1] - fabsf((float)(lr - m - 1))) * 0.125f;
                    tm = fmaxf(tm, fmaxf(x0, x1));
                }
                float ts = 0.f;
#pragma unroll
                for (int g = 0; g < 8; ++g) {
                    int m = mt * 128 + wn * 64 + g * 8 + kq * 2;
                    float x0 = (acc[f][g][2 * sub]     - fabsf((float)(lr - m)))     * 0.125f;
                    float x1 = (acc[f][g][2 * sub + 1] - fabsf((float)(lr - m - 1))) * 0.125f;
                    ts += __expf(x0 - tm) + __expf(x1 - tm);
                }
                int i = 2 * f + sub;
                float nm = fmaxf(Mx[i], tm);
                Sm[i] = Sm[i] * __expf(Mx[i] - nm) + ts * __expf(tm - nm);
                Mx[i] = nm;
            }
    }

    // merge across 4 lanes sharing each row
#pragma unroll
    for (int i = 0; i < 4; ++i) {
#pragma unroll
        for (int o = 1; o <= 2; o <<= 1) {
            float oM = __shfl_xor_sync(0xffffffffu, Mx[i], o);
            float oS = __shfl_xor_sync(0xffffffffu, Sm[i], o);
            float nm = fmaxf(Mx[i], oM);
            Sm[i] = Sm[i] * __expf(Mx[i] - nm) + oS * __expf(oM - nm);
            Mx[i] = nm;
        }
    }
    __syncthreads();
    float* sM = Qs;
    float* sS = Qs + 256;
    if (kq == 0) {
#pragma unroll
        for (int f = 0; f < 2; ++f)
#pragma unroll
            for (int sub = 0; sub < 2; ++sub) {
                int rl = wm * 32 + f * 16 + sub * 8 + row;
                sM[wn * 128 + rl] = Mx[2 * f + sub];
                sS[wn * 128 + rl] = Sm[2 * f + sub];
            }
    }
    __syncthreads();
    if (tid < 128) {
        float M0 = sM[tid], M1 = sM[128 + tid];
        float S0 = sS[tid], S1 = sS[128 + tid];
        float nm = fmaxf(M0, M1);
        float S = S0 * __expf(M0 - nm) + S1 * __expf(M1 - nm);
        gM[bh * L_DIM + l0 + tid] = nm;
        gIS[bh * L_DIM + l0 + tid] = 1.0f / S;
    }
}

// ============================================================================
// Attention pass 2: O^T[m,d] = W^T @ V.
//  - Ws[l][m] (tf32, str 136) is both the S-epilogue output and the k-major
//    A-operand of the O^T MMA.
//  - V consumed raw [d][l] as B-operand (str 132) via cp.async.
//  - Q consumed raw [d][l] via cp.async; cvt at fragment read.
// Pipeline: V(lb) issued before S-MMA; Q(lb+1) issued after Ws sync.
// All tiles 64x128 -> u < 8.
// ============================================================================
__global__ __launch_bounds__(256) void attn_out(
    const float* __restrict__ q, const float* __restrict__ k,
    const float* __restrict__ v, const float* __restrict__ gM,
    const float* __restrict__ gIS, float* __restrict__ hout)
{
    extern __shared__ float smem[];
    float* Qs = smem;                       // raw f32 [d=64][l=128] str 136
    float* Vs = Qs + 64 * 136;              // raw f32 [d=64][l=128] str 132
    float* Ks = Vs + 64 * 132;              // tf32   [d=64][m=128] str 136
    float* Ws = Ks + 64 * 136;              // tf32   [l=128][m=128] str 136

    const long long DL = (long long)D_DIM * L_DIM;
    const int bh = blockIdx.y;
    const int mb = (int)(gridDim.x - 1 - blockIdx.x);
    const int m0 = mb * 128;
    const float* qh = q + (long long)bh * DL;
    const float* kh = k + (long long)bh * DL;
    const float* vh = v + (long long)bh * DL;
    const int tid = threadIdx.x, lane = tid & 31, w = tid >> 5;
    const int wm = w & 3, wn = w >> 2;
    const int row = lane >> 2, kq = lane & 3;

    auto issueQ = [&](int lb) {
#pragma unroll
        for (int u = 0; u < 8; ++u) {
            int idx = tid + u * 256;
            int d = idx >> 5, c = (idx & 31) * 4;
            cp_async16(&Qs[d * 136 + c], &qh[(long long)d * L_DIM + lb * 128 + c]);
        }
        cp_commit();
    };
    auto issueV = [&](int lb) {
#pragma unroll
        for (int u = 0; u < 8; ++u) {
            int idx = tid + u * 256;
            int d = idx >> 5, c = (idx & 31) * 4;
            cp_async16(&Vs[d * 132 + c], &vh[(long long)d * L_DIM + lb * 128 + c]);
        }
        cp_commit();
    };

    issueQ(0);

    // stage K tile (persistent, tf32), full 64x128
#pragma unroll
    for (int u = 0; u < 8; ++u) {
        int idx = tid + u * 256;
        int d = idx >> 5, c = (idx & 31) * 4;
        float4 t = *(const float4*)&kh[(long long)d * L_DIM + m0 + c];
        t.x = cvt_tf32(t.x); t.y = cvt_tf32(t.y);
        t.z = cvt_tf32(t.z); t.w = cvt_tf32(t.w);
        *(float4*)&Ks[d * 136 + c] = t;
    }

    float accO[2][4][4] = {};   // O^T: rows m (wm, f<2), cols d (wn, g<4)

    for (int lb = 0; lb <= mb; ++lb) {
        cp_wait0();             // Q(lb) landed
        __syncthreads();        // Qs visible; prev O-MMA done -> Vs/Ws free
        issueV(lb);             // hidden behind S-MMA + weights

        // S = Q^T K : [l=128][m=128]
        float acc[2][8][4] = {};
#pragma unroll
        for (int ks = 0; ks < 64; ks += 8) {
            uint32_t af[2][4];
#pragma unroll
            for (int f = 0; f < 2; ++f) {
                const float* Ab = &Qs[(ks + kq) * 136 + wm * 32 + f * 16 + row];
                af[f][0] = cvt_tf32_u(Ab[0]);
                af[f][1] = cvt_tf32_u(Ab[8]);
                af[f][2] = cvt_tf32_u(Ab[4 * 136]);
                af[f][3] = cvt_tf32_u(Ab[4 * 136 + 8]);
            }
            uint32_t bf[8][2];
#pragma unroll
            for (int g = 0; g < 8; ++g) {
                const float* Bb = &Ks[(ks + kq) * 136 + wn * 64 + g * 8 + row];
                bf[g][0] = __float_as_uint(Bb[0]);
                bf[g][1] = __float_as_uint(Bb[4 * 136]);
            }
#pragma unroll
            for (int f = 0; f < 2; ++f)
#pragma unroll
                for (int g = 0; g < 8; ++g)
                    mma_tf32(acc[f][g], af[f], bf[g]);
        }

        // softmax weights + triu mask -> Ws[l][m] (tf32)
#pragma unroll
        for (int f = 0; f < 2; ++f)
#pragma unroll
            for (int sub = 0; sub < 2; ++sub) {
                int lloc = wm * 32 + f * 16 + sub * 8 + row;
                int lg = lb * 128 + lloc;
                float Mrow = gM[bh * L_DIM + lg];
                float IS = gIS[bh * L_DIM + lg];
#pragma unroll
                for (int g = 0; g < 8; ++g) {
                    int c = wn * 64 + g * 8 + kq * 2;
                    int mg = m0 + c;
                    float x0 = (acc[f][g][2 * sub]     - fabsf((float)(lg - mg)))     * 0.125f;
                    float x1 = (acc[f][g][2 * sub + 1] - fabsf((float)(lg - mg - 1))) * 0.125f;
                    float w0 = __expf(x0 - Mrow) * IS;
                    float w1 = __expf(x1 - Mrow) * IS;
                    if (lb == mb) {
                        if (lg > mg)     w0 = 0.f;
                        if (lg > mg + 1) w1 = 0.f;
                    }
                    float2 t2;
                    t2.x = cvt_tf32(w0);
                    t2.y = cvt_tf32(w1);
                    *(float2*)&Ws[lloc * 136 + c] = t2;
                }
            }
        __syncthreads();        // Ws ready; Qs reads done
        if (lb < mb) { issueQ(lb + 1); cp_wait1(); }  // V(lb) done, Q(lb+1) in flight
        else         { cp_wait0(); }
        __syncthreads();        // Vs visible

        // O^T += W^T[m x l] @ V[l x d]  (A = Ws k-major, B = raw Vs)
#pragma unroll
        for (int ks = 0; ks < 128; ks += 8) {
            uint32_t af[2][4];
#pragma unroll
            for (int f = 0; f < 2; ++f) {
                const float* Ab = &Ws[(ks + kq) * 136 + wm * 32 + f * 16 + row];
                af[f][0] = __float_as_uint(Ab[0]);
                af[f][1] = __float_as_uint(Ab[8]);
                af[f][2] = __float_as_uint(Ab[4 * 136]);
                af[f][3] = __float_as_uint(Ab[4 * 136 + 8]);
            }
            uint32_t bf[4][2];
#pragma unroll
            for (int g = 0; g < 4; ++g) {
                const float* Bb = &Vs[(wn * 32 + g * 8 + row) * 132 + ks + kq];
                bf[g][0] = cvt_tf32_u(Bb[0]);
                bf[g][1] = cvt_tf32_u(Bb[4]);
            }
#pragma unroll
            for (int f = 0; f < 2; ++f)
#pragma unroll
                for (int g = 0; g < 4; ++g)
                    mma_tf32(accO[f][g], af[f], bf[g]);
        }
    }

    // epilogue: ReLU, transpose-store h[d][m]
#pragma unroll
    for (int f = 0; f < 2; ++f) {
        int rm = m0 + wm * 32 + f * 16 + row;
#pragma unroll
        for (int g = 0; g < 4; ++g) {
            int cd = wn * 32 + g * 8 + kq * 2;
            hout[(long long)bh * DL + (long long)cd * L_DIM + rm]           = fmaxf(accO[f][g][0], 0.f);
            hout[(long long)bh * DL + (long long)(cd + 1) * L_DIM + rm]     = fmaxf(accO[f][g][1], 0.f);
            hout[(long long)bh * DL + (long long)cd * L_DIM + rm + 8]       = fmaxf(accO[f][g][2], 0.f);
            hout[(long long)bh * DL + (long long)(cd + 1) * L_DIM + rm + 8] = fmaxf(accO[f][g][3], 0.f);
        }
    }
}

// ============================================================================
extern "C" void kernel_launch(void* const* d_in, const int* in_sizes, int n_in,
                              void* d_out, int out_size)
{
    (void)in_sizes; (void)n_in; (void)out_size;
    const float* x  = (const float*)d_in[0];
    const float* Wq = (const float*)d_in[1];
    const float* bq = (const float*)d_in[2];
    const float* Wk = (const float*)d_in[3];
    const float* bk = (const float*)d_in[4];
    const float* Wv = (const float*)d_in[5];
    const float* bv = (const float*)d_in[6];
    const float* W1 = (const float*)d_in[7];
    const float* b1 = (const float*)d_in[8];
    const float* W2 = (const float*)d_in[9];
    const float* b2 = (const float*)d_in[10];
    float* out = (float*)d_out;

    float *q, *k, *v, *h, *z, *mx, *is;
    cudaGetSymbolAddress((void**)&q, g_q);
    cudaGetSymbolAddress((void**)&k, g_k);
    cudaGetSymbolAddress((void**)&v, g_v);
    cudaGetSymbolAddress((void**)&h, g_h);
    cudaGetSymbolAddress((void**)&z, g_z);
    cudaGetSymbolAddress((void**)&mx, g_mx);
    cudaGetSymbolAddress((void**)&is, g_is);

    const long long AL = (long long)A_DIM * L_DIM;
    const long long XL = (long long)CIN_DIM * L_DIM;

    const int SMEM1 = (64 * 136 * 3) * 4;                                // 104448 B
    const int SMEM2 = (64 * 136 + 64 * 132 + 64 * 136 + 128 * 136) * 4;  // 173056 B
    cudaFuncSetAttribute(attn_stats, cudaFuncAttributeMaxDynamicSharedMemorySize, SMEM1);
    cudaFuncSetAttribute(attn_out,   cudaFuncAttributeMaxDynamicSharedMemorySize, SMEM2);

    // 1) QKV projections
    dim3 gproj(L_DIM / 128, A_DIM / 128, B_DIM);
    gemm_tc<EPI_BIAS><<<gproj, 256>>>(Wq, x, bq, q, A_DIM, L_DIM, CIN_DIM, 0, XL, AL);
    gemm_tc<EPI_BIAS><<<gproj, 256>>>(Wk, x, bk, k, A_DIM, L_DIM, CIN_DIM, 0, XL, AL);
    gemm_tc<EPI_BIAS><<<gproj, 256>>>(Wv, x, bv, v, A_DIM, L_DIM, CIN_DIM, 0, XL, AL);

    // 2) Fused attention
    attn_stats<<<dim3(8, BH_DIM), 256, SMEM1>>>(q, k, mx, is);
    attn_out<<<dim3(8, BH_DIM), 256, SMEM2>>>(q, k, v, mx, is, h);

    // 3) Final MLP
    dim3 gf(L_DIM / 128, A_DIM / 128, B_DIM);
    gemm_tc<EPI_BIAS_RELU><<<gf, 256>>>(W1, h, b1, z, A_DIM, L_DIM, A_DIM, 0, AL, AL);
    gemm_tc<EPI_BIAS><<<gf, 256>>>(W2, z, b2, out, A_DIM, L_DIM, A_DIM, 0, AL, AL);
}